// round 11
// baseline (speedup 1.0000x reference)
#include <cuda_runtime.h>
#include <cuda_bf16.h>

// AllZeroDigitalFilter: time-varying FIR, y = A0 + w*(A1-A0).
// R10: packed f32x2 FMA (accumulator = (A0,A1)), 8 samples/thread,
//      splatted-x registers reused across tap groups (4 new splats/group).

#define TAPS         50
#define TAPS_PAD     52
#define NGROUPS      (TAPS_PAD / 4)          // 13
#define FRAME_P      80
#define FRAMES_PER_BLOCK 16
#define SAMP_PER_BLOCK   (FRAMES_PER_BLOCK * FRAME_P)    // 1280
#define SAMP_PER_THREAD  8
#define THREADS_PER_BLOCK (SAMP_PER_BLOCK / SAMP_PER_THREAD) // 160
#define XPAD         56                      // mult of 8, >= 51+3
#define X_TILE       (SAMP_PER_BLOCK + XPAD + 8)         // 1344

typedef unsigned long long u64;

__device__ __forceinline__ u64 splat2(float v) {
    u64 r;
    asm("mov.b64 %0, {%1, %1};" : "=l"(r) : "f"(v));
    return r;
}
__device__ __forceinline__ void fma2(u64& acc, u64 a, u64 b) {
    asm("fma.rn.f32x2 %0, %1, %2, %0;" : "+l"(acc) : "l"(a), "l"(b));
}
__device__ __forceinline__ void unpack2(float& lo, float& hi, u64 v) {
    asm("mov.b64 {%0, %1}, %2;" : "=f"(lo), "=f"(hi) : "l"(v));
}

__global__ __launch_bounds__(THREADS_PER_BLOCK)
void azdf_kernel(const float* __restrict__ x,
                 const float* __restrict__ bcoef,
                 float* __restrict__ y,
                 int T, int N)
{
    __shared__ __align__(16) float xs[X_TILE];
    // bpair[r][k] = (b[n0+r][k], b[n0+r+1][k]); rows 16B-aligned (52*8 = 416B)
    __shared__ __align__(16) float2 bpair[FRAMES_PER_BLOCK][TAPS_PAD];

    const int bidx = blockIdx.y;
    const int t0   = blockIdx.x * SAMP_PER_BLOCK;
    const int n0   = blockIdx.x * FRAMES_PER_BLOCK;
    const int tid  = threadIdx.x;

    const float* xg = x + (size_t)bidx * T;
    const float* bg = bcoef + (size_t)bidx * N * TAPS;

    // ---- stage x tile: xs[i] = x[t0 - XPAD + i], zero-padded ----
    if (t0 >= XPAD && t0 + (X_TILE - XPAD) <= T) {
        const float4* src = reinterpret_cast<const float4*>(xg + t0 - XPAD);
        float4* dst = reinterpret_cast<float4*>(xs);
        #pragma unroll
        for (int i = tid; i < X_TILE / 4; i += THREADS_PER_BLOCK)
            dst[i] = src[i];
    } else {
        #pragma unroll
        for (int i = tid; i < X_TILE; i += THREADS_PER_BLOCK) {
            int g = t0 - XPAD + i;
            xs[i] = (g >= 0 && g < T) ? xg[g] : 0.0f;
        }
    }
    // ---- stage interleaved coeff pairs ----
    #pragma unroll
    for (int i = tid; i < FRAMES_PER_BLOCK * TAPS_PAD; i += THREADS_PER_BLOCK) {
        int r = i / TAPS_PAD;
        int k = i - r * TAPS_PAD;
        int n  = n0 + r;     if (n  > N - 1) n  = N - 1;
        int n1 = n0 + r + 1; if (n1 > N - 1) n1 = N - 1;
        float2 p;
        if (k < TAPS) {
            p.x = bg[(size_t)n  * TAPS + k];
            p.y = bg[(size_t)n1 * TAPS + k];
        } else {
            p.x = 0.0f; p.y = 0.0f;
        }
        bpair[r][k] = p;
    }
    __syncthreads();

    const int ls = tid * SAMP_PER_THREAD;   // local sample base (mult of 8)
    const int fr = ls / FRAME_P;            // frame in block
    const int p  = ls - fr * FRAME_P;       // phase (mult of 8)

    const float4* xs4 = reinterpret_cast<const float4*>(xs);
    const ulonglong2* cp2 = reinterpret_cast<const ulonglong2*>(bpair[fr]);

    u64 A[SAMP_PER_THREAD] = {0,0,0,0,0,0,0,0};   // (A0,A1) per sample

    // Window for group g (taps k=4g+j): value = xs[XPAD+ls-4g + (4+s-j)-4]
    //   logical w[i], i=0..11 -> chunks cbase-g-1, cbase-g, cbase-g+1.
    // v[i] = splat2(w[i]) maintained for i=1..11; w0 holds w[0] (splat deferred).
    const int cbase = (XPAD + ls) / 4;
    u64 v[12];
    float w0;
    {
        float4 lo = xs4[cbase - 1];
        float4 md = xs4[cbase];
        float4 hi = xs4[cbase + 1];
        w0 = lo.x;
        v[1] = splat2(lo.y);  v[2] = splat2(lo.z);  v[3]  = splat2(lo.w);
        v[4] = splat2(md.x);  v[5] = splat2(md.y);  v[6]  = splat2(md.z);
        v[7] = splat2(md.w);
        v[8] = splat2(hi.x);  v[9] = splat2(hi.y);  v[10] = splat2(hi.z);
        v[11] = splat2(hi.w);
    }

    #pragma unroll
    for (int g = 0; g < NGROUPS; ++g) {
        ulonglong2 cA = cp2[2 * g];          // coeff pairs taps 4g, 4g+1
        ulonglong2 cB = cp2[2 * g + 1];      // taps 4g+2, 4g+3
        const u64 c[4] = {cA.x, cA.y, cB.x, cB.y};

        #pragma unroll
        for (int j = 0; j < 4; ++j) {
            #pragma unroll
            for (int s = 0; s < SAMP_PER_THREAD; ++s)
                fma2(A[s], v[4 + s - j], c[j]);   // index in 1..11
        }

        if (g < NGROUPS - 1) {
            v[0] = splat2(w0);
            // shift window up by 4 (renamed by ptxas under full unroll)
            #pragma unroll
            for (int i = 11; i >= 4; --i) v[i] = v[i - 4];
            float4 nl = xs4[cbase - g - 2];
            w0   = nl.x;
            v[1] = splat2(nl.y);
            v[2] = splat2(nl.z);
            v[3] = splat2(nl.w);
        }
    }

    // ---- blend and store ----
    float a0[SAMP_PER_THREAD], a1[SAMP_PER_THREAD];
    #pragma unroll
    for (int s = 0; s < SAMP_PER_THREAD; ++s) unpack2(a0[s], a1[s], A[s]);

    const int tglob = t0 + ls;
    const float invP = 1.0f / (float)FRAME_P;
    if (tglob + SAMP_PER_THREAD <= T) {
        float4 r0, r1;
        r0.x = fmaf((float)(p + 0) * invP, a1[0] - a0[0], a0[0]);
        r0.y = fmaf((float)(p + 1) * invP, a1[1] - a0[1], a0[1]);
        r0.z = fmaf((float)(p + 2) * invP, a1[2] - a0[2], a0[2]);
        r0.w = fmaf((float)(p + 3) * invP, a1[3] - a0[3], a0[3]);
        r1.x = fmaf((float)(p + 4) * invP, a1[4] - a0[4], a0[4]);
        r1.y = fmaf((float)(p + 5) * invP, a1[5] - a0[5], a0[5]);
        r1.z = fmaf((float)(p + 6) * invP, a1[6] - a0[6], a0[6]);
        r1.w = fmaf((float)(p + 7) * invP, a1[7] - a0[7], a0[7]);
        float4* out = reinterpret_cast<float4*>(y + (size_t)bidx * T + tglob);
        out[0] = r0;
        out[1] = r1;
    } else {
        #pragma unroll
        for (int s = 0; s < SAMP_PER_THREAD; ++s) {
            int t = tglob + s;
            if (t < T) {
                float ww = (float)(p + s) * invP;
                y[(size_t)bidx * T + t] = fmaf(ww, a1[s] - a0[s], a0[s]);
            }
        }
    }
}

extern "C" void kernel_launch(void* const* d_in, const int* in_sizes, int n_in,
                              void* d_out, int out_size)
{
    const float* x = (const float*)d_in[0];   // (B, T) float32
    const float* b = (const float*)d_in[1];   // (B, N, 50) float32
    float* y = (float*)d_out;                 // (B, T) float32

    const int B = 8;
    const int T = in_sizes[0] / B;
    const int N = in_sizes[1] / (B * TAPS);

    dim3 grid((T + SAMP_PER_BLOCK - 1) / SAMP_PER_BLOCK, B);
    azdf_kernel<<<grid, THREADS_PER_BLOCK>>>(x, b, y, T, N);
}

// round 13
// speedup vs baseline: 1.0489x; 1.0489x over previous
#include <cuda_runtime.h>
#include <cuda_bf16.h>
#include <cstdint>

// AllZeroDigitalFilter: time-varying FIR, y = A0 + w*(A1-A0).
// R12: R6 occupancy config (4 samples/thread, 160 thr, 640-sample tiles)
//      + persistent splat registers (4 new splats/group, shifts renamed)
//      + cp.async x-tile staging.  (R11 + missing <cstdint> fix.)

#define TAPS         50
#define TAPS_PAD     52
#define NGROUPS      (TAPS_PAD / 4)          // 13
#define FRAME_P      80
#define FRAMES_PER_BLOCK 8
#define SAMP_PER_BLOCK   (FRAMES_PER_BLOCK * FRAME_P)   // 640
#define SAMP_PER_THREAD  4
#define THREADS_PER_BLOCK (SAMP_PER_BLOCK / SAMP_PER_THREAD) // 160
#define XPAD         56                      // mult of 8, >= 51+3
#define X_TILE       (SAMP_PER_BLOCK + XPAD + 8)        // 704

typedef unsigned long long u64;
typedef unsigned int u32;

__device__ __forceinline__ u64 splat2(float v) {
    u64 r;
    asm("mov.b64 %0, {%1, %1};" : "=l"(r) : "f"(v));
    return r;
}
__device__ __forceinline__ void fma2(u64& acc, u64 a, u64 b) {
    asm("fma.rn.f32x2 %0, %1, %2, %0;" : "+l"(acc) : "l"(a), "l"(b));
}
__device__ __forceinline__ void unpack2(float& lo, float& hi, u64 v) {
    asm("mov.b64 {%0, %1}, %2;" : "=f"(lo), "=f"(hi) : "l"(v));
}
__device__ __forceinline__ u32 smem_addr32(const void* p) {
    return (u32)__cvta_generic_to_shared(p);
}
__device__ __forceinline__ void cp_async16(u32 saddr, const void* gaddr) {
    asm volatile("cp.async.cg.shared.global [%0], [%1], 16;"
                 :: "r"(saddr), "l"(gaddr) : "memory");
}

__global__ __launch_bounds__(THREADS_PER_BLOCK)
void azdf_kernel(const float* __restrict__ x,
                 const float* __restrict__ bcoef,
                 float* __restrict__ y,
                 int T, int N)
{
    __shared__ __align__(16) float xs[X_TILE];
    // bpair[r][k] = (b[n0+r][k], b[n0+r+1][k]); row = 52*8 = 416 B (16B mult)
    __shared__ __align__(16) float2 bpair[FRAMES_PER_BLOCK][TAPS_PAD];

    const int bidx = blockIdx.y;
    const int t0   = blockIdx.x * SAMP_PER_BLOCK;
    const int n0   = blockIdx.x * FRAMES_PER_BLOCK;
    const int tid  = threadIdx.x;

    const float* xg = x + (size_t)bidx * T;
    const float* bg = bcoef + (size_t)bidx * N * TAPS;

    // ---- stage x tile: xs[i] = x[t0 - XPAD + i], zero-padded ----
    bool used_async = false;
    if (t0 >= XPAD && t0 + (X_TILE - XPAD) <= T) {
        // interior fast path: 16B-aligned (t0-XPAD mult of 8), cp.async
        const float* src = xg + t0 - XPAD;
        #pragma unroll
        for (int i = tid; i < X_TILE / 4; i += THREADS_PER_BLOCK)
            cp_async16(smem_addr32(xs + 4 * i), src + 4 * i);
        asm volatile("cp.async.commit_group;" ::: "memory");
        used_async = true;
    } else {
        #pragma unroll
        for (int i = tid; i < X_TILE; i += THREADS_PER_BLOCK) {
            int g = t0 - XPAD + i;
            xs[i] = (g >= 0 && g < T) ? xg[g] : 0.0f;
        }
    }
    // ---- stage interleaved coeff pairs (overlaps with async x loads) ----
    #pragma unroll
    for (int i = tid; i < FRAMES_PER_BLOCK * TAPS_PAD; i += THREADS_PER_BLOCK) {
        int r = i / TAPS_PAD;
        int k = i - r * TAPS_PAD;
        int n  = n0 + r;     if (n  > N - 1) n  = N - 1;
        int n1 = n0 + r + 1; if (n1 > N - 1) n1 = N - 1;
        float2 p;
        if (k < TAPS) {
            p.x = bg[(size_t)n  * TAPS + k];
            p.y = bg[(size_t)n1 * TAPS + k];
        } else {
            p.x = 0.0f; p.y = 0.0f;
        }
        bpair[r][k] = p;
    }
    if (used_async)
        asm volatile("cp.async.wait_group 0;" ::: "memory");
    __syncthreads();

    const int ls = tid * SAMP_PER_THREAD;   // local sample base (mult of 4)
    const int fr = ls / FRAME_P;            // frame in block
    const int p  = ls - fr * FRAME_P;       // phase (mult of 4)

    const float4* xs4 = reinterpret_cast<const float4*>(xs);
    const ulonglong2* cp2 = reinterpret_cast<const ulonglong2*>(bpair[fr]);

    u64 A[SAMP_PER_THREAD] = {0ull, 0ull, 0ull, 0ull};   // (A0,A1) per sample

    // Window at group g (taps k=4g+j): value = v[4+s-j],
    //   v[m] = splat(xs[XPAD+ls-4g-4+m]), m=0..7.
    // Per group: FMAs use v[1..7]; shift v[4..7]=v[0..3] (renamed), load new
    // chunk -> 4 fresh splats into v[0..3].
    const int cbase = (XPAD + ls) / 4;
    u64 v[8];
    {
        float4 lo = xs4[cbase - 1];
        float4 hi = xs4[cbase];
        v[0] = splat2(lo.x); v[1] = splat2(lo.y);
        v[2] = splat2(lo.z); v[3] = splat2(lo.w);
        v[4] = splat2(hi.x); v[5] = splat2(hi.y);
        v[6] = splat2(hi.z); v[7] = splat2(hi.w);
    }

    #pragma unroll
    for (int g = 0; g < NGROUPS; ++g) {
        ulonglong2 cA = cp2[2 * g];          // coeff pairs taps 4g, 4g+1
        ulonglong2 cB = cp2[2 * g + 1];      // taps 4g+2, 4g+3
        const u64 c[4] = {cA.x, cA.y, cB.x, cB.y};

        #pragma unroll
        for (int j = 0; j < 4; ++j) {
            #pragma unroll
            for (int s = 0; s < SAMP_PER_THREAD; ++s)
                fma2(A[s], v[4 + s - j], c[j]);   // index 1..7
        }

        if (g < NGROUPS - 1) {
            // shift up by 4 (register renaming under full unroll)
            v[7] = v[3]; v[6] = v[2]; v[5] = v[1]; v[4] = v[0];
            float4 nl = xs4[cbase - g - 2];
            v[0] = splat2(nl.x); v[1] = splat2(nl.y);
            v[2] = splat2(nl.z); v[3] = splat2(nl.w);
        }
    }

    // ---- blend and store ----
    float a0[SAMP_PER_THREAD], a1[SAMP_PER_THREAD];
    #pragma unroll
    for (int s = 0; s < SAMP_PER_THREAD; ++s) unpack2(a0[s], a1[s], A[s]);

    const int tglob = t0 + ls;
    const float invP = 1.0f / (float)FRAME_P;
    if (tglob + SAMP_PER_THREAD <= T) {
        float4 r;
        r.x = fmaf((float)(p + 0) * invP, a1[0] - a0[0], a0[0]);
        r.y = fmaf((float)(p + 1) * invP, a1[1] - a0[1], a0[1]);
        r.z = fmaf((float)(p + 2) * invP, a1[2] - a0[2], a0[2]);
        r.w = fmaf((float)(p + 3) * invP, a1[3] - a0[3], a0[3]);
        *reinterpret_cast<float4*>(y + (size_t)bidx * T + tglob) = r;
    } else {
        #pragma unroll
        for (int s = 0; s < SAMP_PER_THREAD; ++s) {
            int t = tglob + s;
            if (t < T) {
                float ww = (float)(p + s) * invP;
                y[(size_t)bidx * T + t] = fmaf(ww, a1[s] - a0[s], a0[s]);
            }
        }
    }
}

extern "C" void kernel_launch(void* const* d_in, const int* in_sizes, int n_in,
                              void* d_out, int out_size)
{
    const float* x = (const float*)d_in[0];   // (B, T) float32
    const float* b = (const float*)d_in[1];   // (B, N, 50) float32
    float* y = (float*)d_out;                 // (B, T) float32

    const int B = 8;
    const int T = in_sizes[0] / B;
    const int N = in_sizes[1] / (B * TAPS);

    dim3 grid((T + SAMP_PER_BLOCK - 1) / SAMP_PER_BLOCK, B);
    azdf_kernel<<<grid, THREADS_PER_BLOCK>>>(x, b, y, T, N);
}